// round 3
// baseline (speedup 1.0000x reference)
#include <cuda_runtime.h>
#include <math.h>

// Problem dims
#define HD 512      // hidden size
#define BD 512      // batch
#define TD 128      // time steps
// GEMM tile
#define BM 64       // batch rows per CTA
#define BU 32       // hidden units per CTA (x4 gates)
#define KT 32       // k-tile

// ---------------- persistent device state ----------------
__device__ float g_h1[2][BD * HD];
__device__ float g_h2[2][BD * HD];
__device__ float g_c1[BD * HD];
__device__ float g_c2[BD * HD];
__device__ float g_b0[4 * HD];
__device__ float g_b1[4 * HD];

// ---------------- activations ----------------
__device__ __forceinline__ float sigf(float z) {
    return 1.0f / (1.0f + __expf(-z));
}
__device__ __forceinline__ float tanhsf(float z) {
    // tanh(x) = 1 - 2/(exp(2x)+1); safe at +/-inf
    float e = __expf(2.0f * z);
    return 1.0f - 2.0f / (e + 1.0f);
}

// ---------------- fused GEMM over (up to) 2 K=512 segments ----------------
// Computes acc[g][b2][uu] = sum_k h[b][k] * w[g*512 + u][k] for this CTA's tile.
// Thread map: tx = tid&7 (8 u-groups * 4u), ty = tid>>3 (32 b-groups * 2b).
__device__ __forceinline__ void gemm_gates(
    const float* __restrict__ hA, const float* __restrict__ wA,
    const float* __restrict__ hB, const float* __restrict__ wB,
    int nseg, float (&acc)[4][2][4], int b0, int u0, int tid)
{
    __shared__ float hs[KT][BM + 2];        // [k][b]
    __shared__ float ws[KT][4 * BU + 4];    // [k][g*32+ul]

    const int r  = tid >> 3;        // 0..31
    const int c4 = (tid & 7) * 4;   // 0,4,...,28
    const int tx = tid & 7;
    const int ty = tid >> 3;

    for (int seg = 0; seg < nseg; ++seg) {
        const float* __restrict__ h = (seg == 0) ? hA : hB;
        const float* __restrict__ w = (seg == 0) ? wA : wB;
        for (int k0 = 0; k0 < HD; k0 += KT) {
            __syncthreads();   // previous compute done before smem overwrite
            // h tile: rows r and r+32
            {
                const float* hp = h + (size_t)(b0 + r) * HD + k0 + c4;
                float4 v0 = *(const float4*)hp;
                float4 v1 = *(const float4*)(hp + 32 * HD);
                hs[c4 + 0][r] = v0.x; hs[c4 + 1][r] = v0.y;
                hs[c4 + 2][r] = v0.z; hs[c4 + 3][r] = v0.w;
                hs[c4 + 0][r + 32] = v1.x; hs[c4 + 1][r + 32] = v1.y;
                hs[c4 + 2][r + 32] = v1.z; hs[c4 + 3][r + 32] = v1.w;
            }
            // w tile: 128 rows (g*32 + ul), 4 passes
            #pragma unroll
            for (int p = 0; p < 4; ++p) {
                int rr = p * 32 + r;           // 0..127
                int g  = rr >> 5;
                int ul = rr & 31;
                const float* wp = w + (size_t)(g * HD + u0 + ul) * HD + k0 + c4;
                float4 v = *(const float4*)wp;
                ws[c4 + 0][rr] = v.x; ws[c4 + 1][rr] = v.y;
                ws[c4 + 2][rr] = v.z; ws[c4 + 3][rr] = v.w;
            }
            __syncthreads();
            #pragma unroll 8
            for (int kk = 0; kk < KT; ++kk) {
                float2 hb = *(const float2*)&hs[kk][ty * 2];
                #pragma unroll
                for (int g = 0; g < 4; ++g) {
                    float4 wv = *(const float4*)&ws[kk][g * BU + tx * 4];
                    acc[g][0][0] += hb.x * wv.x;
                    acc[g][0][1] += hb.x * wv.y;
                    acc[g][0][2] += hb.x * wv.z;
                    acc[g][0][3] += hb.x * wv.w;
                    acc[g][1][0] += hb.y * wv.x;
                    acc[g][1][1] += hb.y * wv.y;
                    acc[g][1][2] += hb.y * wv.z;
                    acc[g][1][3] += hb.y * wv.w;
                }
            }
        }
    }
    __syncthreads();
}

// ---------------- kernels ----------------
__global__ void __launch_bounds__(256) zero_state() {
    int idx = blockIdx.x * 256 + threadIdx.x;   // 1024*256 = 262144 = BD*HD
    g_h1[0][idx] = 0.f; g_h1[1][idx] = 0.f;
    g_h2[0][idx] = 0.f; g_h2[1][idx] = 0.f;
    g_c1[idx] = 0.f;    g_c2[idx] = 0.f;
}

__global__ void __launch_bounds__(256) prep_bias(
    const float* __restrict__ b_ih0, const float* __restrict__ b_hh0,
    const float* __restrict__ b_ih1, const float* __restrict__ b_hh1)
{
    int j = blockIdx.x * 256 + threadIdx.x;     // 8*256 = 2048
    g_b0[j] = b_ih0[j] + b_hh0[j];
    g_b1[j] = b_ih1[j] + b_hh1[j];
}

// Layer 0: gates = x_t * w_ih0 + h1 @ w_hh0^T + b0 ; update (h1, c1).
// Phase-1 mode: xin != nullptr, x_t = xin[b*TD + t].
// AR mode: xin == nullptr: x_t = y = ysrc . w_lin + b_lin (computed here);
//          ysrc = c2 for the FIRST AR step (reference uses state[3] == c2 for y0!),
//          ysrc = h2 for all later steps.
//          CTAs with blockIdx.y==0 also store y into out[b*TD + t_out].
__global__ void __launch_bounds__(256) phaseA(
    int rd,
    const float* __restrict__ w_hh0, const float* __restrict__ w_ih0,
    const float* __restrict__ xin, int t,
    int y_from_c2,
    const float* __restrict__ w_lin, const float* __restrict__ b_lin,
    float* __restrict__ out, int t_out)
{
    const int tid = threadIdx.x;
    const int b0 = blockIdx.x * BM;
    const int u0 = blockIdx.y * BU;

    __shared__ float xs[BM];
    if (xin != nullptr) {
        if (tid < BM) xs[tid] = xin[(size_t)(b0 + tid) * TD + t];
    } else {
        // y = ysrc . w_lin + b_lin ; 4 lanes per batch row
        const float* __restrict__ ysrc = y_from_c2 ? g_c2 : g_h2[rd];
        int rrow = tid >> 2, p = tid & 3;
        const float* hr = ysrc + (size_t)(b0 + rrow) * HD;
        float sum = 0.f;
        #pragma unroll 8
        for (int k = p; k < HD; k += 4) sum += hr[k] * w_lin[k];
        sum += __shfl_xor_sync(0xffffffffu, sum, 1);
        sum += __shfl_xor_sync(0xffffffffu, sum, 2);
        if (p == 0) {
            float yv = sum + b_lin[0];
            xs[rrow] = yv;
            if (blockIdx.y == 0) out[(size_t)(b0 + rrow) * TD + t_out] = yv;
        }
    }
    // gemm_gates starts with __syncthreads(), making xs visible before use.

    float acc[4][2][4] = {};
    gemm_gates(g_h1[rd], w_hh0, nullptr, nullptr, 1, acc, b0, u0, tid);

    float* __restrict__ hw = g_h1[rd ^ 1];
    const int tx = tid & 7, ty = tid >> 3;
    #pragma unroll
    for (int b2 = 0; b2 < 2; ++b2) {
        int b = b0 + ty * 2 + b2;
        float xi = xs[ty * 2 + b2];
        #pragma unroll
        for (int uu = 0; uu < 4; ++uu) {
            int u = u0 + tx * 4 + uu;
            float iv = acc[0][b2][uu] + g_b0[u]          + xi * w_ih0[u];
            float fv = acc[1][b2][uu] + g_b0[HD + u]     + xi * w_ih0[HD + u];
            float gv = acc[2][b2][uu] + g_b0[2 * HD + u] + xi * w_ih0[2 * HD + u];
            float ov = acc[3][b2][uu] + g_b0[3 * HD + u] + xi * w_ih0[3 * HD + u];
            float ig = sigf(iv), fg = sigf(fv), gg = tanhsf(gv), og = sigf(ov);
            size_t idx = (size_t)b * HD + u;
            float cn = fg * g_c1[idx] + ig * gg;
            g_c1[idx] = cn;
            hw[idx] = og * tanhsf(cn);
        }
    }
}

// Layer 1: gates = h1_new @ w_ih1^T + h2_old @ w_hh1^T + b1 ; update (h2, c2).
__global__ void __launch_bounds__(256) phaseB(
    int rd,
    const float* __restrict__ w_ih1, const float* __restrict__ w_hh1)
{
    const int tid = threadIdx.x;
    const int b0 = blockIdx.x * BM;
    const int u0 = blockIdx.y * BU;

    float acc[4][2][4] = {};
    gemm_gates(g_h1[rd ^ 1], w_ih1, g_h2[rd], w_hh1, 2, acc, b0, u0, tid);

    float* __restrict__ hw = g_h2[rd ^ 1];
    const int tx = tid & 7, ty = tid >> 3;
    #pragma unroll
    for (int b2 = 0; b2 < 2; ++b2) {
        int b = b0 + ty * 2 + b2;
        #pragma unroll
        for (int uu = 0; uu < 4; ++uu) {
            int u = u0 + tx * 4 + uu;
            float iv = acc[0][b2][uu] + g_b1[u];
            float fv = acc[1][b2][uu] + g_b1[HD + u];
            float gv = acc[2][b2][uu] + g_b1[2 * HD + u];
            float ov = acc[3][b2][uu] + g_b1[3 * HD + u];
            float ig = sigf(iv), fg = sigf(fv), gg = tanhsf(gv), og = sigf(ov);
            size_t idx = (size_t)b * HD + u;
            float cn = fg * g_c2[idx] + ig * gg;
            g_c2[idx] = cn;
            hw[idx] = og * tanhsf(cn);
        }
    }
}

// Final prediction y_{T-1} -> out[:, TD-1]  (from h2, matching ar_step's y_new)
__global__ void __launch_bounds__(256) final_y(
    int rd, const float* __restrict__ w_lin, const float* __restrict__ b_lin,
    float* __restrict__ out)
{
    const int tid = threadIdx.x;
    int rrow = blockIdx.x * 64 + (tid >> 2);   // 8 CTAs * 64 rows
    int p = tid & 3;
    const float* hr = g_h2[rd] + (size_t)rrow * HD;
    float sum = 0.f;
    #pragma unroll 8
    for (int k = p; k < HD; k += 4) sum += hr[k] * w_lin[k];
    sum += __shfl_xor_sync(0xffffffffu, sum, 1);
    sum += __shfl_xor_sync(0xffffffffu, sum, 2);
    if (p == 0) out[(size_t)rrow * TD + (TD - 1)] = sum + b_lin[0];
}

// ---------------- host launcher ----------------
extern "C" void kernel_launch(void* const* d_in, const int* in_sizes, int n_in,
                              void* d_out, int out_size)
{
    const float* x     = (const float*)d_in[0];
    // d_in[1] x_time, d_in[2] y_time: unused
    const float* w_ih0 = (const float*)d_in[3];
    const float* w_hh0 = (const float*)d_in[4];
    const float* b_ih0 = (const float*)d_in[5];
    const float* b_hh0 = (const float*)d_in[6];
    const float* w_ih1 = (const float*)d_in[7];
    const float* w_hh1 = (const float*)d_in[8];
    const float* b_ih1 = (const float*)d_in[9];
    const float* b_hh1 = (const float*)d_in[10];
    const float* w_lin = (const float*)d_in[11];
    const float* b_lin = (const float*)d_in[12];
    float* out = (float*)d_out;

    zero_state<<<1024, 256>>>();
    prep_bias<<<8, 256>>>(b_ih0, b_hh0, b_ih1, b_hh1);

    dim3 grid(BD / BM, HD / BU);   // (8, 16) = 128 CTAs
    dim3 blk(256);

    int s = 0;
    // Phase 1: teacher-forced over T steps
    for (int t = 0; t < TD; ++t, ++s) {
        phaseA<<<grid, blk>>>(s & 1, w_hh0, w_ih0, x, t,
                              0, nullptr, nullptr, nullptr, 0);
        phaseB<<<grid, blk>>>(s & 1, w_ih1, w_hh1);
    }
    // Phase 2: autoregressive (computes y_{i-1}, stores out[:, i-1], feeds it back)
    // NOTE: first AR input y0 comes from c2 (reference uses state[3] == c2),
    // all later predictions come from h2.
    for (int i = 1; i < TD; ++i, ++s) {
        phaseA<<<grid, blk>>>(s & 1, w_hh0, w_ih0, nullptr, 0,
                              (i == 1) ? 1 : 0, w_lin, b_lin, out, i - 1);
        phaseB<<<grid, blk>>>(s & 1, w_ih1, w_hh1);
    }
    // Last prediction
    final_y<<<8, 256>>>(s & 1, w_lin, b_lin, out);
}

// round 6
// speedup vs baseline: 3.3479x; 3.3479x over previous
#include <cuda_runtime.h>
#include <cuda_bf16.h>
#include <stdint.h>
#include <math.h>

// ---------------- dims ----------------
#define HD 512
#define BD 512
#define TD 128

#define MB 64        // batch rows per CTA (M)
#define NB 128       // N per CTA = 4 gates x 32 units
#define NU 32        // units per CTA
#define KC 64        // k per stage

// smem stage layout (bytes), rows padded to 144B (64 k bf16 = 128B data + 16B pad)
#define ROWB 144
#define A_BYTES (64 * ROWB)        // 9216
#define W_BYTES (128 * ROWB)       // 18432
#define OFF_ALO A_BYTES
#define OFF_WHI (2 * A_BYTES)
#define OFF_WLO (2 * A_BYTES + W_BYTES)
#define STAGE_BYTES (2 * A_BYTES + 2 * W_BYTES)   // 55296
#define OFF_XS (2 * STAGE_BYTES)
#define SMEM_TOTAL (OFF_XS + 1024)

// ---------------- persistent device state ----------------
__device__ float g_c1[BD*HD];
__device__ float g_c2[BD*HD];
__device__ float g_h2f[2][BD*HD];
__device__ __align__(16) __nv_bfloat16 g_h1hi[2][BD*HD], g_h1lo[2][BD*HD];
__device__ __align__(16) __nv_bfloat16 g_h2hi[2][BD*HD], g_h2lo[2][BD*HD];
__device__ float g_b0[4*HD], g_b1[4*HD];
__device__ __align__(16) __nv_bfloat16 g_whh0hi[4*HD*HD], g_whh0lo[4*HD*HD];
__device__ __align__(16) __nv_bfloat16 g_wih1hi[4*HD*HD], g_wih1lo[4*HD*HD];
__device__ __align__(16) __nv_bfloat16 g_whh1hi[4*HD*HD], g_whh1lo[4*HD*HD];

// ---------------- helpers ----------------
__device__ __forceinline__ uint32_t smem_u32(const void* p) {
    uint32_t a;
    asm("{ .reg .u64 t; cvta.to.shared.u64 t, %1; cvt.u32.u64 %0, t; }" : "=r"(a) : "l"(p));
    return a;
}
__device__ __forceinline__ void cpa16(uint32_t dst, const void* src) {
    asm volatile("cp.async.cg.shared.global [%0], [%1], 16;" :: "r"(dst), "l"(src));
}
#define CP_COMMIT() asm volatile("cp.async.commit_group;")
#define CP_WAIT(n)  asm volatile("cp.async.wait_group %0;" :: "n"(n))

__device__ __forceinline__ void ldm4(uint32_t (&r)[4], uint32_t addr) {
    asm volatile("ldmatrix.sync.aligned.m8n8.x4.shared.b16 {%0,%1,%2,%3}, [%4];"
        : "=r"(r[0]), "=r"(r[1]), "=r"(r[2]), "=r"(r[3]) : "r"(addr));
}
__device__ __forceinline__ void mma16816(float (&d)[4], const uint32_t a[4], const uint32_t b[2]) {
    asm volatile("mma.sync.aligned.m16n8k16.row.col.f32.bf16.bf16.f32 "
        "{%0,%1,%2,%3}, {%4,%5,%6,%7}, {%8,%9}, {%0,%1,%2,%3};"
        : "+f"(d[0]), "+f"(d[1]), "+f"(d[2]), "+f"(d[3])
        : "r"(a[0]), "r"(a[1]), "r"(a[2]), "r"(a[3]), "r"(b[0]), "r"(b[1]));
}

__device__ __forceinline__ float sigf(float z) { return 1.0f / (1.0f + __expf(-z)); }
__device__ __forceinline__ float tanhsf(float z) {
    float e = __expf(2.0f * z);
    return 1.0f - 2.0f / (e + 1.0f);
}

// ---------------- stage loader: A(hi,lo) 64xKC, W(hi,lo) 128xKC ----------------
__device__ __forceinline__ void stage_load(uint32_t st,
    const __nv_bfloat16* __restrict__ ahi, const __nv_bfloat16* __restrict__ alo,
    const __nv_bfloat16* __restrict__ whi, const __nv_bfloat16* __restrict__ wlo,
    int b0, int u0, int k0, int tid)
{
    #pragma unroll
    for (int q = 0; q < 2; q++) {
        int i = tid + q * 256;
        int r = i >> 3, s = (i & 7) * 8;           // s in bf16 elems (16B chunks)
        uint32_t doff = (uint32_t)(r * ROWB + s * 2);
        size_t goff = (size_t)(b0 + r) * HD + k0 + s;
        cpa16(st + doff,            ahi + goff);
        cpa16(st + OFF_ALO + doff,  alo + goff);
    }
    #pragma unroll
    for (int q = 0; q < 4; q++) {
        int i = tid + q * 256;
        int n = i >> 3, s = (i & 7) * 8;
        int wrow = ((n >> 5) << 9) + u0 + (n & 31);  // gate*512 + u
        uint32_t doff = (uint32_t)(n * ROWB + s * 2);
        size_t goff = (size_t)wrow * HD + k0 + s;
        cpa16(st + OFF_WHI + doff, whi + goff);
        cpa16(st + OFF_WLO + doff, wlo + goff);
    }
}

// ---------------- compute one 64-k stage: 3 products into d ----------------
__device__ __forceinline__ void compute_stage(uint32_t sbase, float (&d)[2][4][4],
                                              int wm, int wn, int lane)
{
    const int l7 = lane & 7, grp = lane >> 3;
    const uint32_t a_row = (uint32_t)(((grp & 1) << 3) + l7);
    const uint32_t a_kb  = (uint32_t)((grp >> 1) << 4);
    const uint32_t b_n   = (uint32_t)(((grp >> 1) << 3) + l7);
    const uint32_t b_kb  = (uint32_t)((grp & 1) << 4);

    #pragma unroll
    for (int kk = 0; kk < 4; kk++) {
        uint32_t kb = kk * 32;   // bytes: k16 step = 32B
        uint32_t Ah[2][4], Al[2][4], Bh[2][4], Bl[2][4];
        #pragma unroll
        for (int mi = 0; mi < 2; mi++) {
            uint32_t ra = sbase + (wm * 32 + mi * 16 + a_row) * ROWB + kb + a_kb;
            ldm4(Ah[mi], ra);
            ldm4(Al[mi], ra + OFF_ALO);
        }
        #pragma unroll
        for (int p = 0; p < 2; p++) {
            uint32_t rb = sbase + OFF_WHI + (wn * 32 + p * 16 + b_n) * ROWB + kb + b_kb;
            ldm4(Bh[p], rb);
            ldm4(Bl[p], rb + W_BYTES);
        }
        #pragma unroll
        for (int mi = 0; mi < 2; mi++) {
            #pragma unroll
            for (int ni = 0; ni < 4; ni++) {
                const uint32_t* bh = &Bh[ni >> 1][(ni & 1) * 2];
                const uint32_t* bl = &Bl[ni >> 1][(ni & 1) * 2];
                mma16816(d[mi][ni], Ah[mi], bh);
                mma16816(d[mi][ni], Al[mi], bh);
                mma16816(d[mi][ni], Ah[mi], bl);
            }
        }
    }
}

// ---------------- accum -> smem gate buffer ----------------
__device__ __forceinline__ void store_gbuf(float* gbuf, float (&d)[2][4][4],
                                           int wm, int wn, int lane)
{
    const int gid = lane >> 2, tig = lane & 3;
    #pragma unroll
    for (int mi = 0; mi < 2; mi++) {
        #pragma unroll
        for (int ni = 0; ni < 4; ni++) {
            int row = wm * 32 + mi * 16 + gid;
            int c0 = wn * 32 + ni * 8 + tig * 2;
            gbuf[row * 132 + c0]           = d[mi][ni][0];
            gbuf[row * 132 + c0 + 1]       = d[mi][ni][1];
            gbuf[(row + 8) * 132 + c0]     = d[mi][ni][2];
            gbuf[(row + 8) * 132 + c0 + 1] = d[mi][ni][3];
        }
    }
}

// ---------------- setup kernels ----------------
__global__ void __launch_bounds__(256) zero_state() {
    int idx = blockIdx.x * 256 + threadIdx.x;   // grid 1024
    g_c1[idx] = 0.f; g_c2[idx] = 0.f;
    __nv_bfloat16 z = __float2bfloat16(0.f);
    g_h1hi[0][idx] = z; g_h1lo[0][idx] = z;
    g_h2hi[0][idx] = z; g_h2lo[0][idx] = z;
}
__global__ void __launch_bounds__(256) prep_bias(
    const float* __restrict__ b_ih0, const float* __restrict__ b_hh0,
    const float* __restrict__ b_ih1, const float* __restrict__ b_hh1) {
    int j = blockIdx.x * 256 + threadIdx.x;     // grid 8
    g_b0[j] = b_ih0[j] + b_hh0[j];
    g_b1[j] = b_ih1[j] + b_hh1[j];
}
__global__ void __launch_bounds__(256) splitw(const float* __restrict__ w, int which) {
    __nv_bfloat16 *hi, *lo;
    if (which == 0)      { hi = g_whh0hi; lo = g_whh0lo; }
    else if (which == 1) { hi = g_wih1hi; lo = g_wih1lo; }
    else                 { hi = g_whh1hi; lo = g_whh1lo; }
    int i = blockIdx.x * 256 + threadIdx.x;     // grid 4096
    float v = w[i];
    __nv_bfloat16 h = __float2bfloat16(v);
    hi[i] = h;
    lo[i] = __float2bfloat16(v - __bfloat162float(h));
}

// ---------------- phase A: layer-0 step ----------------
__global__ void __launch_bounds__(256) phaseA_k(
    int rd, const float* __restrict__ xin, int t, int y_from_c2,
    const float* __restrict__ w_lin, const float* __restrict__ b_lin,
    float* __restrict__ out, int t_out, const float* __restrict__ w_ih0)
{
    extern __shared__ char sm[];
    uint32_t sb = smem_u32(sm);
    const int tid = threadIdx.x, lane = tid & 31, wid = tid >> 5;
    const int wm = wid >> 2, wn = wid & 3;
    const int b0 = blockIdx.x * MB, u0 = blockIdx.y * NU;
    float* xs = (float*)(sm + OFF_XS);

    // input scalar per batch row (teacher-forced or autoregressive)
    if (xin != nullptr) {
        if (tid < MB) xs[tid] = xin[(size_t)(b0 + tid) * TD + t];
    } else {
        const float* ysrc = y_from_c2 ? g_c2 : g_h2f[rd];
        int rrow = tid >> 2, p = tid & 3;
        const float4* hr = (const float4*)(ysrc + (size_t)(b0 + rrow) * HD);
        const float4* wl = (const float4*)w_lin;
        float s = 0.f;
        #pragma unroll 8
        for (int kk = p; kk < HD / 4; kk += 4) {
            float4 a = hr[kk]; float4 w = wl[kk];
            s += a.x * w.x + a.y * w.y + a.z * w.z + a.w * w.w;
        }
        s += __shfl_xor_sync(0xffffffffu, s, 1);
        s += __shfl_xor_sync(0xffffffffu, s, 2);
        if (p == 0) {
            float yv = s + b_lin[0];
            xs[rrow] = yv;
            if (blockIdx.y == 0) out[(size_t)(b0 + rrow) * TD + t_out] = yv;
        }
    }

    const __nv_bfloat16* ahi = g_h1hi[rd];
    const __nv_bfloat16* alo = g_h1lo[rd];
    float d[2][4][4] = {};

    stage_load(sb, ahi, alo, g_whh0hi, g_whh0lo, b0, u0, 0, tid);
    CP_COMMIT();
    #pragma unroll 1
    for (int i = 0; i < 8; i++) {
        if (i + 1 < 8) {
            stage_load(sb + ((i + 1) & 1) * STAGE_BYTES, ahi, alo, g_whh0hi, g_whh0lo,
                       b0, u0, (i + 1) * KC, tid);
            CP_COMMIT();
            CP_WAIT(1);
        } else {
            CP_WAIT(0);
        }
        __syncthreads();
        compute_stage(sb + (i & 1) * STAGE_BYTES, d, wm, wn, lane);
        __syncthreads();
    }

    float* gbuf = (float*)sm;
    store_gbuf(gbuf, d, wm, wn, lane);
    __syncthreads();

    // cell update: thread -> (row, 8 consecutive u)
    {
        int row = tid >> 2, ub = (tid & 3) * 8;
        float xi = xs[row];
        size_t rowbase = (size_t)(b0 + row) * HD + u0 + ub;
        float4 ca = *(const float4*)(g_c1 + rowbase);
        float4 cb = *(const float4*)(g_c1 + rowbase + 4);
        float cv[8] = {ca.x, ca.y, ca.z, ca.w, cb.x, cb.y, cb.z, cb.w};
        __align__(16) __nv_bfloat16 hh[8], hl[8];
        #pragma unroll
        for (int j = 0; j < 8; j++) {
            int ul = ub + j;
            int ug = u0 + ul;
            float iv = gbuf[row * 132 + ul]       + g_b0[ug]          + xi * w_ih0[ug];
            float fv = gbuf[row * 132 + 32 + ul]  + g_b0[HD + ug]     + xi * w_ih0[HD + ug];
            float gv = gbuf[row * 132 + 64 + ul]  + g_b0[2*HD + ug]   + xi * w_ih0[2*HD + ug];
            float ov = gbuf[row * 132 + 96 + ul]  + g_b0[3*HD + ug]   + xi * w_ih0[3*HD + ug];
            float cn = sigf(fv) * cv[j] + sigf(iv) * tanhsf(gv);
            cv[j] = cn;
            float h = sigf(ov) * tanhsf(cn);
            hh[j] = __float2bfloat16(h);
            hl[j] = __float2bfloat16(h - __bfloat162float(hh[j]));
        }
        *(float4*)(g_c1 + rowbase)     = make_float4(cv[0], cv[1], cv[2], cv[3]);
        *(float4*)(g_c1 + rowbase + 4) = make_float4(cv[4], cv[5], cv[6], cv[7]);
        *(uint4*)(g_h1hi[rd ^ 1] + rowbase) = *(const uint4*)hh;
        *(uint4*)(g_h1lo[rd ^ 1] + rowbase) = *(const uint4*)hl;
    }
}

// ---------------- phase B: layer-1 step (K=1024, two segments) ----------------
__global__ void __launch_bounds__(256) phaseB_k(int rd)
{
    extern __shared__ char sm[];
    uint32_t sb = smem_u32(sm);
    const int tid = threadIdx.x, lane = tid & 31, wid = tid >> 5;
    const int wm = wid >> 2, wn = wid & 3;
    const int b0 = blockIdx.x * MB, u0 = blockIdx.y * NU;

    const __nv_bfloat16* AH[2] = { g_h1hi[rd ^ 1], g_h2hi[rd] };
    const __nv_bfloat16* AL[2] = { g_h1lo[rd ^ 1], g_h2lo[rd] };
    const __nv_bfloat16* WH[2] = { g_wih1hi, g_whh1hi };
    const __nv_bfloat16* WL[2] = { g_wih1lo, g_whh1lo };

    float d[2][4][4] = {};

    stage_load(sb, AH[0], AL[0], WH[0], WL[0], b0, u0, 0, tid);
    CP_COMMIT();
    #pragma unroll 1
    for (int i = 0; i < 16; i++) {
        if (i + 1 < 16) {
            int sg = (i + 1) >> 3, k0 = ((i + 1) & 7) * KC;
            stage_load(sb + ((i + 1) & 1) * STAGE_BYTES, AH[sg], AL[sg], WH[sg], WL[sg],
                       b0, u0, k0, tid);
            CP_COMMIT();
            CP_WAIT(1);
        } else {
            CP_WAIT(0);
        }
        __syncthreads();
        compute_stage(sb + (i & 1) * STAGE_BYTES, d, wm, wn, lane);
        __syncthreads();
    }

    float* gbuf = (float*)sm;
    store_gbuf(gbuf, d, wm, wn, lane);
    __syncthreads();

    {
        int row = tid >> 2, ub = (tid & 3) * 8;
        size_t rowbase = (size_t)(b0 + row) * HD + u0 + ub;
        float4 ca = *(const float4*)(g_c2 + rowbase);
        float4 cb = *(const float4*)(g_c2 + rowbase + 4);
        float cv[8] = {ca.x, ca.y, ca.z, ca.w, cb.x, cb.y, cb.z, cb.w};
        float hv[8];
        __align__(16) __nv_bfloat16 hh[8], hl[8];
        #pragma unroll
        for (int j = 0; j < 8; j++) {
            int ul = ub + j;
            int ug = u0 + ul;
            float iv = gbuf[row * 132 + ul]      + g_b1[ug];
            float fv = gbuf[row * 132 + 32 + ul] + g_b1[HD + ug];
            float gv = gbuf[row * 132 + 64 + ul] + g_b1[2*HD + ug];
            float ov = gbuf[row * 132 + 96 + ul] + g_b1[3*HD + ug];
            float cn = sigf(fv) * cv[j] + sigf(iv) * tanhsf(gv);
            cv[j] = cn;
            float h = sigf(ov) * tanhsf(cn);
            hv[j] = h;
            hh[j] = __float2bfloat16(h);
            hl[j] = __float2bfloat16(h - __bfloat162float(hh[j]));
        }
        *(float4*)(g_c2 + rowbase)     = make_float4(cv[0], cv[1], cv[2], cv[3]);
        *(float4*)(g_c2 + rowbase + 4) = make_float4(cv[4], cv[5], cv[6], cv[7]);
        *(float4*)(g_h2f[rd ^ 1] + rowbase)     = make_float4(hv[0], hv[1], hv[2], hv[3]);
        *(float4*)(g_h2f[rd ^ 1] + rowbase + 4) = make_float4(hv[4], hv[5], hv[6], hv[7]);
        *(uint4*)(g_h2hi[rd ^ 1] + rowbase) = *(const uint4*)hh;
        *(uint4*)(g_h2lo[rd ^ 1] + rowbase) = *(const uint4*)hl;
    }
}

// ---------------- final prediction ----------------
__global__ void __launch_bounds__(256) final_y(
    int rd, const float* __restrict__ w_lin, const float* __restrict__ b_lin,
    float* __restrict__ out)
{
    int tid = threadIdx.x;
    int rrow = blockIdx.x * 128 + (tid >> 1);   // grid 4
    int p = tid & 1;
    const float4* hr = (const float4*)(g_h2f[rd] + (size_t)rrow * HD);
    const float4* wl = (const float4*)w_lin;
    float s = 0.f;
    #pragma unroll 16
    for (int kk = p; kk < HD / 4; kk += 2) {
        float4 a = hr[kk]; float4 w = wl[kk];
        s += a.x * w.x + a.y * w.y + a.z * w.z + a.w * w.w;
    }
    s += __shfl_xor_sync(0xffffffffu, s, 1);
    if (p == 0) out[(size_t)rrow * TD + (TD - 1)] = s + b_lin[0];
}

// ---------------- host launcher ----------------
extern "C" void kernel_launch(void* const* d_in, const int* in_sizes, int n_in,
                              void* d_out, int out_size)
{
    const float* x     = (const float*)d_in[0];
    const float* w_ih0 = (const float*)d_in[3];
    const float* w_hh0 = (const float*)d_in[4];
    const float* b_ih0 = (const float*)d_in[5];
    const float* b_hh0 = (const float*)d_in[6];
    const float* w_ih1 = (const float*)d_in[7];
    const float* w_hh1 = (const float*)d_in[8];
    const float* b_ih1 = (const float*)d_in[9];
    const float* b_hh1 = (const float*)d_in[10];
    const float* w_lin = (const float*)d_in[11];
    const float* b_lin = (const float*)d_in[12];
    float* out = (float*)d_out;

    cudaFuncSetAttribute(phaseA_k, cudaFuncAttributeMaxDynamicSharedMemorySize, SMEM_TOTAL);
    cudaFuncSetAttribute(phaseB_k, cudaFuncAttributeMaxDynamicSharedMemorySize, SMEM_TOTAL);

    zero_state<<<1024, 256>>>();
    prep_bias<<<8, 256>>>(b_ih0, b_hh0, b_ih1, b_hh1);
    splitw<<<4096, 256>>>(w_hh0, 0);
    splitw<<<4096, 256>>>(w_ih1, 1);
    splitw<<<4096, 256>>>(w_hh1, 2);

    dim3 grid(BD / MB, HD / NU);   // (8, 16) = 128 CTAs
    int s = 0;
    for (int t = 0; t < TD; ++t, ++s) {
        phaseA_k<<<grid, 256, SMEM_TOTAL>>>(s & 1, x, t, 0,
                                            nullptr, nullptr, nullptr, 0, w_ih0);
        phaseB_k<<<grid, 256, SMEM_TOTAL>>>(s & 1);
    }
    for (int i = 1; i < TD; ++i, ++s) {
        phaseA_k<<<grid, 256, SMEM_TOTAL>>>(s & 1, nullptr, 0, (i == 1) ? 1 : 0,
                                            w_lin, b_lin, out, i - 1, w_ih0);
        phaseB_k<<<grid, 256, SMEM_TOTAL>>>(s & 1);
    }
    final_y<<<4, 256>>>(s & 1, w_lin, b_lin, out);
}